// round 14
// baseline (speedup 1.0000x reference)
#include <cuda_runtime.h>
#include <cuda_fp16.h>

#define S 8
#define N 512
#define C 128
#define H 128
#define W 128
#define LEVELS 4
#define KK 49
#define OUT_F 972
#define PLANE_ELEMS 22282240   // (8*(128*128+64*64+32*32+16*16)) * 128

// Scratch: channel-last fp16 fmap pyramid per plane (static device global)
__device__ __half g_pyr[3][PLANE_ELEMS];

// Level offsets in "position" units (positions * C = element offset)
// L0: 0        (S*16384)
// L1: 131072   (S*4096)
// L2: 163840   (S*1024)
// L3: 172032   (S*256)

// ---------------------------------------------------------------------------
// 1) Fused transpose + L1 pool: [S,C,H,W] fp32 -> [S,H,W,C] fp16 L0 + fp16 L1
//    Block covers (s, h-pair) x (32c x 32w tile). grid (S*64, 16, 3)
// ---------------------------------------------------------------------------
__global__ void transpose_pool_kernel(const float* __restrict__ in0,
                                      const float* __restrict__ in1,
                                      const float* __restrict__ in2) {
    int plane = blockIdx.z;
    const float* __restrict__ in = (plane == 0) ? in0 : (plane == 1) ? in1 : in2;
    __half* __restrict__ out = g_pyr[plane];

    int shp = blockIdx.x;            // s*64 + hp
    int s = shp >> 6;
    int hp = shp & 63;               // h-pair: rows 2hp, 2hp+1
    int tileid = blockIdx.y;
    int c0 = (tileid >> 2) * 32;
    int w0 = (tileid & 3) * 32;

    __shared__ float t0[32][33];     // [c_off][w_off] row 2hp
    __shared__ float t1[32][33];     // row 2hp+1
    int tx = threadIdx.x, ty = threadIdx.y;   // (32, 8)

    const float* __restrict__ inp = in + (size_t)s * C * H * W + (size_t)(2 * hp) * W;
#pragma unroll
    for (int i = 0; i < 32; i += 8) {
        t0[ty + i][tx] = inp[(size_t)(c0 + ty + i) * (H * W) + (w0 + tx)];
        t1[ty + i][tx] = inp[(size_t)(c0 + ty + i) * (H * W) + W + (w0 + tx)];
    }
    __syncthreads();

    // L0 writes (channel-last, fp16, half2-packed: 512 half2 per row buffer)
    __half* __restrict__ o0 = out + (size_t)(s * H + 2 * hp) * W * C;
    __half* __restrict__ o1 = o0 + (size_t)W * C;
    int tid = ty * 32 + tx;
#pragma unroll
    for (int k = 0; k < 2; ++k) {
        int idx = tid + k * 256;         // 0..511
        int wo = idx >> 4;               // 0..31
        int c = (idx & 15) * 2;          // 0,2,..,30
        __half2 v0 = __floats2half2_rn(t0[c][wo], t0[c + 1][wo]);
        __half2 v1 = __floats2half2_rn(t1[c][wo], t1[c + 1][wo]);
        *(__half2*)(o0 + (size_t)(w0 + wo) * C + (c0 + c)) = v0;
        *(__half2*)(o1 + (size_t)(w0 + wo) * C + (c0 + c)) = v1;
    }

    // L1 writes: pool 2x2 in fp32, store fp16
    const long L1o = 131072L;
#pragma unroll
    for (int k = 0; k < 2; ++k) {
        int wp = ty + k * 8;                    // 0..15
        float v = t0[tx][2 * wp] + t0[tx][2 * wp + 1]
                + t1[tx][2 * wp] + t1[tx][2 * wp + 1];
        long pos = L1o + (((long)s * 64 + hp) * 64 + (w0 >> 1) + wp);
        out[pos * C + (c0 + tx)] = __float2half(0.25f * v);
    }
}

// ---------------------------------------------------------------------------
// helpers: uint2 = 4 halves
// ---------------------------------------------------------------------------
__device__ __forceinline__ void h4_to_f(uint2 u, float* f) {
    float2 a = __half22float2(*(__half2*)&u.x);
    float2 b = __half22float2(*(__half2*)&u.y);
    f[0] = a.x; f[1] = a.y; f[2] = b.x; f[3] = b.y;
}

// ---------------------------------------------------------------------------
// 2) Fused L1->L2->L3 pool (fp16 in/out, fp32 math). grid (S*16,1,3), 256 thr
// ---------------------------------------------------------------------------
__global__ __launch_bounds__(256) void pool23_kernel() {
    int plane = blockIdx.z;
    int idx = blockIdx.x;              // s*16 + r
    int sfr = idx >> 4;
    int r = idx & 15;
    __half* __restrict__ base = g_pyr[plane];
    const long L1o = 131072L, L2o = 163840L, L3o = 172032L;

    __shared__ float s2[2][32][C];     // L2 values fp32 [row2][col][c] (32 KB)
    int tid = threadIdx.x;
    int warp = tid >> 5, lane = tid & 31;

    // L2: 64 positions (2 rows x 32 cols); warp handles 8; lane = 4 channels
#pragma unroll
    for (int i = 0; i < 8; ++i) {
        int p = warp * 8 + i;
        int row2 = p >> 5, col2 = p & 31;
        int gr2 = r * 2 + row2;
        long l1p = L1o + (((long)sfr * 64 + gr2 * 2) * 64 + col2 * 2);
        float a[4], b[4], c[4], d[4];
        h4_to_f(((const uint2*)(base + l1p * C))[lane], a);
        h4_to_f(((const uint2*)(base + (l1p + 1) * C))[lane], b);
        h4_to_f(((const uint2*)(base + (l1p + 64) * C))[lane], c);
        h4_to_f(((const uint2*)(base + (l1p + 65) * C))[lane], d);
        float v[4];
        __half2 h01, h23;
#pragma unroll
        for (int j = 0; j < 4; ++j) v[j] = 0.25f * (a[j] + b[j] + c[j] + d[j]);
        h01 = __floats2half2_rn(v[0], v[1]);
        h23 = __floats2half2_rn(v[2], v[3]);
        long l2p = L2o + (((long)sfr * 32 + gr2) * 32 + col2);
        uint2 packed = { *(unsigned*)&h01, *(unsigned*)&h23 };
        ((uint2*)(base + l2p * C))[lane] = packed;
#pragma unroll
        for (int j = 0; j < 4; ++j) s2[row2][col2][lane * 4 + j] = v[j];
    }
    __syncthreads();

    // L3: 16 positions in row r; warp handles 2; lane = 4 channels
#pragma unroll
    for (int i = 0; i < 2; ++i) {
        int p = warp * 2 + i;          // col3 0..15
        float v[4];
#pragma unroll
        for (int j = 0; j < 4; ++j) {
            int cc = lane * 4 + j;
            v[j] = 0.25f * (s2[0][2 * p][cc] + s2[0][2 * p + 1][cc]
                          + s2[1][2 * p][cc] + s2[1][2 * p + 1][cc]);
        }
        __half2 h01 = __floats2half2_rn(v[0], v[1]);
        __half2 h23 = __floats2half2_rn(v[2], v[3]);
        long l3p = L3o + (((long)sfr * 16 + r) * 16 + p);
        uint2 packed = { *(unsigned*)&h01, *(unsigned*)&h23 };
        ((uint2*)(base + l3p * C))[lane] = packed;
    }
}

// ---------------------------------------------------------------------------
// 3) Main: per (plane, s, n). Warp l owns level l. 4 positions/iter,
//    8-lane reduction (3 shfls). grid (S*N, 3), 128 threads.
// ---------------------------------------------------------------------------
__global__ __launch_bounds__(128) void main_kernel(const float* __restrict__ coords,
                                                   const int* __restrict__ qt,
                                                   float* __restrict__ out) {
    const long LOFF[4] = {0L, 131072L, 163840L, 172032L};
    const float INV_SQRT_C = 0.08838834764831845f;   // 1/sqrt(128)

    int plane = blockIdx.y;
    int sn = blockIdx.x;                  // s*N + n
    int n = sn & (N - 1);
    int sfr = sn >> 9;
    int tid = threadIdx.x;
    int warp = tid >> 5, lane = tid & 31;
    int sub4 = lane >> 3;                 // which of 4 positions this octet reads
    int lh8  = lane & 7;                  // lane within octet

    __shared__ float t_sh[C];
    __shared__ float patch[4][64];

    const __half* __restrict__ pbase = g_pyr[plane];

    float cx, cy;
    {
        const float* __restrict__ cp = coords + (long)sn * 3;
        float x = cp[0], y = cp[1], z = cp[2];
        if (plane == 0)      { cx = x; cy = y; }
        else if (plane == 1) { cx = y; cy = z; }
        else                 { cx = x; cy = z; }
    }

    // --- inline tfeat: bilinear at frame qt[n] with frame-0 coords ---
    {
        const float* __restrict__ cp0 = coords + (long)n * 3;   // s = 0
        float x = cp0[0], y = cp0[1], z = cp0[2];
        float fx, fy;
        if (plane == 0)      { fx = x; fy = y; }
        else if (plane == 1) { fx = y; fy = z; }
        else                 { fx = x; fy = z; }
        fx = fminf(fmaxf(fx, 0.f), (float)(W - 1));
        fy = fminf(fmaxf(fy, 0.f), (float)(H - 1));
        int qx0 = min((int)floorf(fx), W - 2);
        int qy0 = min((int)floorf(fy), H - 2);
        float wx = fx - (float)qx0, wy = fy - (float)qy0;
        int t = qt[n];
        const __half* __restrict__ b = pbase + (((long)t * H + qy0) * W + qx0) * C + tid;
        float v00 = __half2float(b[0]), v01 = __half2float(b[C]);
        float v10 = __half2float(b[(long)W * C]), v11 = __half2float(b[(long)W * C + C]);
        t_sh[tid] = v00 * (1.f - wx) * (1.f - wy) + v01 * wx * (1.f - wy)
                  + v10 * (1.f - wx) * wy + v11 * wx * wy;
    }
    __syncthreads();
    // 16 target channels for this lane: [lh8*8..+7] and [64+lh8*8..+7]
    float4 tA0 = *(const float4*)&t_sh[lh8 * 8];
    float4 tA1 = *(const float4*)&t_sh[lh8 * 8 + 4];
    float4 tB0 = *(const float4*)&t_sh[64 + lh8 * 8];
    float4 tB1 = *(const float4*)&t_sh[64 + lh8 * 8 + 4];

    float* __restrict__ outcorr = out + (long)sn * OUT_F + plane * (LEVELS * KK);

    // --- warp 'warp' handles level l = warp ---
    {
        int l = warp;
        int Wl = W >> l;
        float inv = 1.0f / (float)(1 << l);
        float cxl = cx * inv, cyl = cy * inv;

        // patch base corner (tap j=0)
        float xs0 = fminf(fmaxf(cxl - 3.f, 0.f), (float)(Wl - 1));
        int xb = min((int)floorf(xs0), Wl - 2);
        float ys0 = fminf(fmaxf(cyl - 3.f, 0.f), (float)(Wl - 1));
        int yb = min((int)floorf(ys0), Wl - 2);

        long fr = LOFF[l] + (long)sfr * Wl * Wl;

        // 64 patch dots; 4 positions per iter (one per lane-octet)
#pragma unroll 8
        for (int i = 0; i < 16; ++i) {
            int p = i * 4 + sub4;
            int iy = p >> 3, ix = p & 7;
            int xx = min(xb + ix, Wl - 1);
            int yy = min(yb + iy, Wl - 1);
            const __half* __restrict__ pp = pbase + (fr + (long)yy * Wl + xx) * C;
            const uint4 uA = *(const uint4*)(pp + lh8 * 8);
            const uint4 uB = *(const uint4*)(pp + 64 + lh8 * 8);
            float2 a0 = __half22float2(*(const __half2*)&uA.x);
            float2 a1 = __half22float2(*(const __half2*)&uA.y);
            float2 a2 = __half22float2(*(const __half2*)&uA.z);
            float2 a3 = __half22float2(*(const __half2*)&uA.w);
            float2 b0 = __half22float2(*(const __half2*)&uB.x);
            float2 b1 = __half22float2(*(const __half2*)&uB.y);
            float2 b2 = __half22float2(*(const __half2*)&uB.z);
            float2 b3 = __half22float2(*(const __half2*)&uB.w);
            float d = a0.x * tA0.x + a0.y * tA0.y + a1.x * tA0.z + a1.y * tA0.w
                    + a2.x * tA1.x + a2.y * tA1.y + a3.x * tA1.z + a3.y * tA1.w
                    + b0.x * tB0.x + b0.y * tB0.y + b1.x * tB0.z + b1.y * tB0.w
                    + b2.x * tB1.x + b2.y * tB1.y + b3.x * tB1.z + b3.y * tB1.w;
            d += __shfl_xor_sync(0xffffffffu, d, 4);
            d += __shfl_xor_sync(0xffffffffu, d, 2);
            d += __shfl_xor_sync(0xffffffffu, d, 1);
            if (lh8 == 0) patch[l][p] = d * INV_SQRT_C;
        }
        __syncwarp();

        // 49 bilinear taps; weights recomputed scalar per tap
        const float* __restrict__ pl = patch[l];
#pragma unroll
        for (int k0 = 0; k0 < 64; k0 += 32) {
            int k = k0 + lane;
            if (k < KK) {
                int ky = k / 7, kx = k - ky * 7;
                float xsk = fminf(fmaxf(cxl + (float)(kx - 3), 0.f), (float)(Wl - 1));
                int xk0 = min((int)floorf(xsk), Wl - 2);
                float wx = xsk - (float)xk0;
                float ysk = fminf(fmaxf(cyl + (float)(ky - 3), 0.f), (float)(Wl - 1));
                int yk0 = min((int)floorf(ysk), Wl - 2);
                float wy = ysk - (float)yk0;
                int ix = xk0 - xb, iy = yk0 - yb;
                float v = pl[iy * 8 + ix]           * (1.f - wx) * (1.f - wy)
                        + pl[iy * 8 + ix + 1]       * wx         * (1.f - wy)
                        + pl[(iy + 1) * 8 + ix]     * (1.f - wx) * wy
                        + pl[(iy + 1) * 8 + ix + 1] * wx         * wy;
                outcorr[l * KK + k] = v;
            }
        }
    }

    // current triplane feature: bilinear at level 0, frame s (independent of patch)
    {
        float xs = fminf(fmaxf(cx, 0.f), (float)(W - 1));
        float ys = fminf(fmaxf(cy, 0.f), (float)(H - 1));
        int x0 = min((int)floorf(xs), W - 2);
        int y0 = min((int)floorf(ys), H - 2);
        float wx = xs - (float)x0, wy = ys - (float)y0;
        const __half* __restrict__ b = pbase + (((long)sfr * H + y0) * W + x0) * C + tid;
        float v00 = __half2float(b[0]), v01 = __half2float(b[C]);
        float v10 = __half2float(b[(long)W * C]), v11 = __half2float(b[(long)W * C + C]);
        float v = v00 * (1.f - wx) * (1.f - wy) + v01 * wx * (1.f - wy)
                + v10 * (1.f - wx) * wy + v11 * wx * wy;
        out[(long)sn * OUT_F + 3 * LEVELS * KK + plane * C + tid] = v;
    }
}

// ---------------------------------------------------------------------------
extern "C" void kernel_launch(void* const* d_in, const int* in_sizes, int n_in,
                              void* d_out, int out_size) {
    const float* fxy    = (const float*)d_in[0];
    const float* fyz    = (const float*)d_in[1];
    const float* fxz    = (const float*)d_in[2];
    const float* coords = (const float*)d_in[3];
    const int*   qt     = (const int*)d_in[4];
    float* out = (float*)d_out;
    (void)in_sizes; (void)n_in; (void)out_size;

    // 1) fused transpose + L1 pool (fp32 -> fp16)
    {
        dim3 grid(S * 64, 16, 3), block(32, 8);
        transpose_pool_kernel<<<grid, block>>>(fxy, fyz, fxz);
    }
    // 2) fused L2+L3 pools
    {
        dim3 grid(S * 16, 1, 3);
        pool23_kernel<<<grid, 256>>>();
    }
    // 3) main lookup (tfeat inlined, warp-per-level)
    {
        dim3 grid(S * N, 3);
        main_kernel<<<grid, 128>>>(coords, qt, out);
    }
}

// round 15
// speedup vs baseline: 1.2089x; 1.2089x over previous
#include <cuda_runtime.h>
#include <cuda_fp16.h>

#define S 8
#define N 512
#define C 128
#define H 128
#define W 128
#define LEVELS 4
#define KK 49
#define OUT_F 972
#define PLANE_ELEMS 22282240   // (8*(128*128+64*64+32*32+16*16)) * 128

// Scratch: channel-last fp16 fmap pyramid per plane (static device global)
__device__ __half g_pyr[3][PLANE_ELEMS];

// Level offsets in "position" units (positions * C = element offset)
// L0: 0        (S*16384)
// L1: 131072   (S*4096)
// L2: 163840   (S*1024)
// L3: 172032   (S*256)

// ---------------------------------------------------------------------------
// 1) Fused transpose + L1 pool: [S,C,H,W] fp32 -> [S,H,W,C] fp16 L0 + fp16 L1
//    Block covers (s, h-pair) x (32c x 32w tile). grid (S*64, 16, 3)
// ---------------------------------------------------------------------------
__global__ void transpose_pool_kernel(const float* __restrict__ in0,
                                      const float* __restrict__ in1,
                                      const float* __restrict__ in2) {
    int plane = blockIdx.z;
    const float* __restrict__ in = (plane == 0) ? in0 : (plane == 1) ? in1 : in2;
    __half* __restrict__ out = g_pyr[plane];

    int shp = blockIdx.x;            // s*64 + hp
    int s = shp >> 6;
    int hp = shp & 63;               // h-pair: rows 2hp, 2hp+1
    int tileid = blockIdx.y;
    int c0 = (tileid >> 2) * 32;
    int w0 = (tileid & 3) * 32;

    __shared__ float t0[32][33];     // [c_off][w_off] row 2hp
    __shared__ float t1[32][33];     // row 2hp+1
    int tx = threadIdx.x, ty = threadIdx.y;   // (32, 8)

    const float* __restrict__ inp = in + (size_t)s * C * H * W + (size_t)(2 * hp) * W;
#pragma unroll
    for (int i = 0; i < 32; i += 8) {
        t0[ty + i][tx] = inp[(size_t)(c0 + ty + i) * (H * W) + (w0 + tx)];
        t1[ty + i][tx] = inp[(size_t)(c0 + ty + i) * (H * W) + W + (w0 + tx)];
    }
    __syncthreads();

    // L0 writes (channel-last, fp16)
    __half* __restrict__ o0 = out + (size_t)(s * H + 2 * hp) * W * C;
    __half* __restrict__ o1 = o0 + (size_t)W * C;
#pragma unroll
    for (int i = 0; i < 32; i += 8) {
        o0[(size_t)(w0 + ty + i) * C + (c0 + tx)] = __float2half(t0[tx][ty + i]);
        o1[(size_t)(w0 + ty + i) * C + (c0 + tx)] = __float2half(t1[tx][ty + i]);
    }

    // L1 writes: pool 2x2 in fp32, store fp16
    const long L1o = 131072L;
#pragma unroll
    for (int k = 0; k < 2; ++k) {
        int wp = ty + k * 8;                    // 0..15
        float v = t0[tx][2 * wp] + t0[tx][2 * wp + 1]
                + t1[tx][2 * wp] + t1[tx][2 * wp + 1];
        long pos = L1o + (((long)s * 64 + hp) * 64 + (w0 >> 1) + wp);
        out[pos * C + (c0 + tx)] = __float2half(0.25f * v);
    }
}

// ---------------------------------------------------------------------------
// helpers: uint2 = 4 halves
// ---------------------------------------------------------------------------
__device__ __forceinline__ void h4_to_f(uint2 u, float* f) {
    float2 a = __half22float2(*(__half2*)&u.x);
    float2 b = __half22float2(*(__half2*)&u.y);
    f[0] = a.x; f[1] = a.y; f[2] = b.x; f[3] = b.y;
}

// ---------------------------------------------------------------------------
// 2) Fused L1->L2->L3 pool (fp16 in/out, fp32 math). grid (S*16,1,3), 256 thr
// ---------------------------------------------------------------------------
__global__ __launch_bounds__(256) void pool23_kernel() {
    int plane = blockIdx.z;
    int idx = blockIdx.x;              // s*16 + r
    int sfr = idx >> 4;
    int r = idx & 15;
    __half* __restrict__ base = g_pyr[plane];
    const long L1o = 131072L, L2o = 163840L, L3o = 172032L;

    __shared__ float s2[2][32][C];     // L2 values fp32 [row2][col][c] (32 KB)
    int tid = threadIdx.x;
    int warp = tid >> 5, lane = tid & 31;

    // L2: 64 positions (2 rows x 32 cols); warp handles 8; lane = 4 channels
#pragma unroll
    for (int i = 0; i < 8; ++i) {
        int p = warp * 8 + i;
        int row2 = p >> 5, col2 = p & 31;
        int gr2 = r * 2 + row2;
        long l1p = L1o + (((long)sfr * 64 + gr2 * 2) * 64 + col2 * 2);
        float a[4], b[4], c[4], d[4];
        h4_to_f(((const uint2*)(base + l1p * C))[lane], a);
        h4_to_f(((const uint2*)(base + (l1p + 1) * C))[lane], b);
        h4_to_f(((const uint2*)(base + (l1p + 64) * C))[lane], c);
        h4_to_f(((const uint2*)(base + (l1p + 65) * C))[lane], d);
        float v[4];
        __half2 h01, h23;
#pragma unroll
        for (int j = 0; j < 4; ++j) v[j] = 0.25f * (a[j] + b[j] + c[j] + d[j]);
        h01 = __floats2half2_rn(v[0], v[1]);
        h23 = __floats2half2_rn(v[2], v[3]);
        long l2p = L2o + (((long)sfr * 32 + gr2) * 32 + col2);
        uint2 packed = { *(unsigned*)&h01, *(unsigned*)&h23 };
        ((uint2*)(base + l2p * C))[lane] = packed;
#pragma unroll
        for (int j = 0; j < 4; ++j) s2[row2][col2][lane * 4 + j] = v[j];
    }
    __syncthreads();

    // L3: 16 positions in row r; warp handles 2; lane = 4 channels
#pragma unroll
    for (int i = 0; i < 2; ++i) {
        int p = warp * 2 + i;          // col3 0..15
        float v[4];
#pragma unroll
        for (int j = 0; j < 4; ++j) {
            int cc = lane * 4 + j;
            v[j] = 0.25f * (s2[0][2 * p][cc] + s2[0][2 * p + 1][cc]
                          + s2[1][2 * p][cc] + s2[1][2 * p + 1][cc]);
        }
        __half2 h01 = __floats2half2_rn(v[0], v[1]);
        __half2 h23 = __floats2half2_rn(v[2], v[3]);
        long l3p = L3o + (((long)sfr * 16 + r) * 16 + p);
        uint2 packed = { *(unsigned*)&h01, *(unsigned*)&h23 };
        ((uint2*)(base + l3p * C))[lane] = packed;
    }
}

// ---------------------------------------------------------------------------
// 3) Main: per (plane, s, n). Warp l owns pyramid level l end-to-end:
//    64 patch dots -> private patch slice -> 49 bilinear taps. Feat loads
//    hoisted above the gather loop. grid (S*N, 3), 128 threads.
// ---------------------------------------------------------------------------
__global__ __launch_bounds__(128) void main_kernel(const float* __restrict__ coords,
                                                   const int* __restrict__ qt,
                                                   float* __restrict__ out) {
    const long LOFF[4] = {0L, 131072L, 163840L, 172032L};
    const float INV_SQRT_C = 0.08838834764831845f;   // 1/sqrt(128)

    int plane = blockIdx.y;
    int sn = blockIdx.x;                  // s*N + n
    int n = sn & (N - 1);
    int sfr = sn >> 9;
    int tid = threadIdx.x;
    int warp = tid >> 5, lane = tid & 31;
    int sub = lane >> 4;                  // which of 2 positions this half-warp reads
    int lh  = lane & 15;                  // lane within half-warp: channels lh*8..+7

    __shared__ float t_sh[C];
    __shared__ float patch[4][64];

    const __half* __restrict__ pbase = g_pyr[plane];

    float cx, cy;
    {
        const float* __restrict__ cp = coords + (long)sn * 3;
        float x = cp[0], y = cp[1], z = cp[2];
        if (plane == 0)      { cx = x; cy = y; }
        else if (plane == 1) { cx = y; cy = z; }
        else                 { cx = x; cy = z; }
    }

    // --- inline tfeat: bilinear at frame qt[n] with frame-0 coords ---
    {
        const float* __restrict__ cp0 = coords + (long)n * 3;   // s = 0
        float x = cp0[0], y = cp0[1], z = cp0[2];
        float fx, fy;
        if (plane == 0)      { fx = x; fy = y; }
        else if (plane == 1) { fx = y; fy = z; }
        else                 { fx = x; fy = z; }
        fx = fminf(fmaxf(fx, 0.f), (float)(W - 1));
        fy = fminf(fmaxf(fy, 0.f), (float)(H - 1));
        int qx0 = min((int)floorf(fx), W - 2);
        int qy0 = min((int)floorf(fy), H - 2);
        float wx = fx - (float)qx0, wy = fy - (float)qy0;
        int t = qt[n];
        const __half* __restrict__ b = pbase + (((long)t * H + qy0) * W + qx0) * C + tid;
        float v00 = __half2float(b[0]), v01 = __half2float(b[C]);
        float v10 = __half2float(b[(long)W * C]), v11 = __half2float(b[(long)W * C + C]);
        t_sh[tid] = v00 * (1.f - wx) * (1.f - wy) + v01 * wx * (1.f - wy)
                  + v10 * (1.f - wx) * wy + v11 * wx * wy;
    }
    __syncthreads();
    // 8 target channels for this lane's slice
    float4 tA = *(const float4*)&t_sh[lh * 8];
    float4 tB = *(const float4*)&t_sh[lh * 8 + 4];

    // --- hoist current-feature bilinear loads (independent of patch loop) ---
    float fwx, fwy;
    __half h00, h01h, h10, h11;
    {
        float xs = fminf(fmaxf(cx, 0.f), (float)(W - 1));
        float ys = fminf(fmaxf(cy, 0.f), (float)(H - 1));
        int x0 = min((int)floorf(xs), W - 2);
        int y0 = min((int)floorf(ys), H - 2);
        fwx = xs - (float)x0; fwy = ys - (float)y0;
        const __half* __restrict__ b = pbase + (((long)sfr * H + y0) * W + x0) * C + tid;
        h00 = b[0]; h01h = b[C];
        h10 = b[(long)W * C]; h11 = b[(long)W * C + C];
    }

    float* __restrict__ outcorr = out + (long)sn * OUT_F + plane * (LEVELS * KK);

    // --- warp 'warp' handles level l = warp ---
    {
        int l = warp;
        int Wl = W >> l;
        float inv = 1.0f / (float)(1 << l);
        float cxl = cx * inv, cyl = cy * inv;

        // patch base corner (tap j=0)
        float xs0 = fminf(fmaxf(cxl - 3.f, 0.f), (float)(Wl - 1));
        int xb = min((int)floorf(xs0), Wl - 2);
        float ys0 = fminf(fmaxf(cyl - 3.f, 0.f), (float)(Wl - 1));
        int yb = min((int)floorf(ys0), Wl - 2);

        long fr = LOFF[l] + (long)sfr * Wl * Wl;

        // 64 patch dots; 2 positions per iter (one per half-warp)
#pragma unroll 8
        for (int i = 0; i < 32; ++i) {
            int p = i * 2 + sub;
            int iy = p >> 3, ix = p & 7;
            int xx = min(xb + ix, Wl - 1);
            int yy = min(yb + iy, Wl - 1);
            const uint4 u = *(const uint4*)(pbase + (fr + (long)yy * Wl + xx) * C + lh * 8);
            float2 f0 = __half22float2(*(const __half2*)&u.x);
            float2 f1 = __half22float2(*(const __half2*)&u.y);
            float2 f2 = __half22float2(*(const __half2*)&u.z);
            float2 f3 = __half22float2(*(const __half2*)&u.w);
            float d = f0.x * tA.x + f0.y * tA.y + f1.x * tA.z + f1.y * tA.w
                    + f2.x * tB.x + f2.y * tB.y + f3.x * tB.z + f3.y * tB.w;
            d += __shfl_xor_sync(0xffffffffu, d, 8);
            d += __shfl_xor_sync(0xffffffffu, d, 4);
            d += __shfl_xor_sync(0xffffffffu, d, 2);
            d += __shfl_xor_sync(0xffffffffu, d, 1);
            if (lh == 0) patch[l][p] = d * INV_SQRT_C;
        }
        __syncwarp();

        // 49 bilinear taps; weights recomputed scalar per tap
        const float* __restrict__ pl = patch[l];
#pragma unroll
        for (int k0 = 0; k0 < 64; k0 += 32) {
            int k = k0 + lane;
            if (k < KK) {
                int ky = k / 7, kx = k - ky * 7;
                float xsk = fminf(fmaxf(cxl + (float)(kx - 3), 0.f), (float)(Wl - 1));
                int xk0 = min((int)floorf(xsk), Wl - 2);
                float wx = xsk - (float)xk0;
                float ysk = fminf(fmaxf(cyl + (float)(ky - 3), 0.f), (float)(Wl - 1));
                int yk0 = min((int)floorf(ysk), Wl - 2);
                float wy = ysk - (float)yk0;
                int ix = xk0 - xb, iy = yk0 - yb;
                float v = pl[iy * 8 + ix]           * (1.f - wx) * (1.f - wy)
                        + pl[iy * 8 + ix + 1]       * wx         * (1.f - wy)
                        + pl[(iy + 1) * 8 + ix]     * (1.f - wx) * wy
                        + pl[(iy + 1) * 8 + ix + 1] * wx         * wy;
                outcorr[l * KK + k] = v;
            }
        }
    }

    // current triplane feature: combine hoisted loads and store
    {
        float v00 = __half2float(h00), v01 = __half2float(h01h);
        float v10 = __half2float(h10), v11 = __half2float(h11);
        float v = v00 * (1.f - fwx) * (1.f - fwy) + v01 * fwx * (1.f - fwy)
                + v10 * (1.f - fwx) * fwy + v11 * fwx * fwy;
        out[(long)sn * OUT_F + 3 * LEVELS * KK + plane * C + tid] = v;
    }
}

// ---------------------------------------------------------------------------
extern "C" void kernel_launch(void* const* d_in, const int* in_sizes, int n_in,
                              void* d_out, int out_size) {
    const float* fxy    = (const float*)d_in[0];
    const float* fyz    = (const float*)d_in[1];
    const float* fxz    = (const float*)d_in[2];
    const float* coords = (const float*)d_in[3];
    const int*   qt     = (const int*)d_in[4];
    float* out = (float*)d_out;
    (void)in_sizes; (void)n_in; (void)out_size;

    // 1) fused transpose + L1 pool (fp32 -> fp16)
    {
        dim3 grid(S * 64, 16, 3), block(32, 8);
        transpose_pool_kernel<<<grid, block>>>(fxy, fyz, fxz);
    }
    // 2) fused L2+L3 pools
    {
        dim3 grid(S * 16, 1, 3);
        pool23_kernel<<<grid, 256>>>();
    }
    // 3) main lookup (tfeat inlined, warp-per-level, feat loads hoisted)
    {
        dim3 grid(S * N, 3);
        main_kernel<<<grid, 128>>>(coords, qt, out);
    }
}

// round 16
// speedup vs baseline: 1.3361x; 1.1052x over previous
#include <cuda_runtime.h>
#include <cuda_fp16.h>

#define S 8
#define N 512
#define C 128
#define H 128
#define W 128
#define LEVELS 4
#define KK 49
#define OUT_F 972
#define PLANE_ELEMS 22282240   // (8*(128*128+64*64+32*32+16*16)) * 128

// Scratch: channel-last fp16 fmap pyramid per plane (static device global)
__device__ __half g_pyr[3][PLANE_ELEMS];

// Level offsets in "position" units (positions * C = element offset)
// L0: 0        (S*16384)
// L1: 131072   (S*4096)
// L2: 163840   (S*1024)
// L3: 172032   (S*256)

// ---------------------------------------------------------------------------
// 1) Fused transpose + L1 pool: [S,C,H,W] fp32 -> [S,H,W,C] fp16 L0 + fp16 L1
//    Block covers (s, h-pair) x (32c x 32w tile). grid (S*64, 16, 3)
// ---------------------------------------------------------------------------
__global__ void transpose_pool_kernel(const float* __restrict__ in0,
                                      const float* __restrict__ in1,
                                      const float* __restrict__ in2) {
    int plane = blockIdx.z;
    const float* __restrict__ in = (plane == 0) ? in0 : (plane == 1) ? in1 : in2;
    __half* __restrict__ out = g_pyr[plane];

    int shp = blockIdx.x;            // s*64 + hp
    int s = shp >> 6;
    int hp = shp & 63;               // h-pair: rows 2hp, 2hp+1
    int tileid = blockIdx.y;
    int c0 = (tileid >> 2) * 32;
    int w0 = (tileid & 3) * 32;

    __shared__ float t0[32][33];     // [c_off][w_off] row 2hp
    __shared__ float t1[32][33];     // row 2hp+1
    int tx = threadIdx.x, ty = threadIdx.y;   // (32, 8)

    const float* __restrict__ inp = in + (size_t)s * C * H * W + (size_t)(2 * hp) * W;
#pragma unroll
    for (int i = 0; i < 32; i += 8) {
        t0[ty + i][tx] = inp[(size_t)(c0 + ty + i) * (H * W) + (w0 + tx)];
        t1[ty + i][tx] = inp[(size_t)(c0 + ty + i) * (H * W) + W + (w0 + tx)];
    }
    __syncthreads();

    // L0 writes (channel-last, fp16)
    __half* __restrict__ o0 = out + (size_t)(s * H + 2 * hp) * W * C;
    __half* __restrict__ o1 = o0 + (size_t)W * C;
#pragma unroll
    for (int i = 0; i < 32; i += 8) {
        o0[(size_t)(w0 + ty + i) * C + (c0 + tx)] = __float2half(t0[tx][ty + i]);
        o1[(size_t)(w0 + ty + i) * C + (c0 + tx)] = __float2half(t1[tx][ty + i]);
    }

    // L1 writes: pool 2x2 in fp32, store fp16
    const long L1o = 131072L;
#pragma unroll
    for (int k = 0; k < 2; ++k) {
        int wp = ty + k * 8;                    // 0..15
        float v = t0[tx][2 * wp] + t0[tx][2 * wp + 1]
                + t1[tx][2 * wp] + t1[tx][2 * wp + 1];
        long pos = L1o + (((long)s * 64 + hp) * 64 + (w0 >> 1) + wp);
        out[pos * C + (c0 + tx)] = __float2half(0.25f * v);
    }
}

// ---------------------------------------------------------------------------
// helpers: uint2 = 4 halves
// ---------------------------------------------------------------------------
__device__ __forceinline__ void h4_to_f(uint2 u, float* f) {
    float2 a = __half22float2(*(__half2*)&u.x);
    float2 b = __half22float2(*(__half2*)&u.y);
    f[0] = a.x; f[1] = a.y; f[2] = b.x; f[3] = b.y;
}

// ---------------------------------------------------------------------------
// 2) Fused L1->L2->L3 pool (fp16 in/out, fp32 math). grid (S*16,1,3), 256 thr
// ---------------------------------------------------------------------------
__global__ __launch_bounds__(256) void pool23_kernel() {
    int plane = blockIdx.z;
    int idx = blockIdx.x;              // s*16 + r
    int sfr = idx >> 4;
    int r = idx & 15;
    __half* __restrict__ base = g_pyr[plane];
    const long L1o = 131072L, L2o = 163840L, L3o = 172032L;

    __shared__ float s2[2][32][C];     // L2 values fp32 [row2][col][c] (32 KB)
    int tid = threadIdx.x;
    int warp = tid >> 5, lane = tid & 31;

    // L2: 64 positions (2 rows x 32 cols); warp handles 8; lane = 4 channels
#pragma unroll
    for (int i = 0; i < 8; ++i) {
        int p = warp * 8 + i;
        int row2 = p >> 5, col2 = p & 31;
        int gr2 = r * 2 + row2;
        long l1p = L1o + (((long)sfr * 64 + gr2 * 2) * 64 + col2 * 2);
        float a[4], b[4], c[4], d[4];
        h4_to_f(((const uint2*)(base + l1p * C))[lane], a);
        h4_to_f(((const uint2*)(base + (l1p + 1) * C))[lane], b);
        h4_to_f(((const uint2*)(base + (l1p + 64) * C))[lane], c);
        h4_to_f(((const uint2*)(base + (l1p + 65) * C))[lane], d);
        float v[4];
        __half2 h01, h23;
#pragma unroll
        for (int j = 0; j < 4; ++j) v[j] = 0.25f * (a[j] + b[j] + c[j] + d[j]);
        h01 = __floats2half2_rn(v[0], v[1]);
        h23 = __floats2half2_rn(v[2], v[3]);
        long l2p = L2o + (((long)sfr * 32 + gr2) * 32 + col2);
        uint2 packed = { *(unsigned*)&h01, *(unsigned*)&h23 };
        ((uint2*)(base + l2p * C))[lane] = packed;
#pragma unroll
        for (int j = 0; j < 4; ++j) s2[row2][col2][lane * 4 + j] = v[j];
    }
    __syncthreads();

    // L3: 16 positions in row r; warp handles 2; lane = 4 channels
#pragma unroll
    for (int i = 0; i < 2; ++i) {
        int p = warp * 2 + i;          // col3 0..15
        float v[4];
#pragma unroll
        for (int j = 0; j < 4; ++j) {
            int cc = lane * 4 + j;
            v[j] = 0.25f * (s2[0][2 * p][cc] + s2[0][2 * p + 1][cc]
                          + s2[1][2 * p][cc] + s2[1][2 * p + 1][cc]);
        }
        __half2 h01 = __floats2half2_rn(v[0], v[1]);
        __half2 h23 = __floats2half2_rn(v[2], v[3]);
        long l3p = L3o + (((long)sfr * 16 + r) * 16 + p);
        uint2 packed = { *(unsigned*)&h01, *(unsigned*)&h23 };
        ((uint2*)(base + l3p * C))[lane] = packed;
    }
}

// ---------------------------------------------------------------------------
// 3) Main: per (plane, s, n). Warp l owns pyramid level l end-to-end:
//    64 patch dots -> private patch slice -> 49 bilinear taps. No block syncs
//    between levels. grid (S*N, 3), 128 threads.
// ---------------------------------------------------------------------------
__global__ __launch_bounds__(128) void main_kernel(const float* __restrict__ coords,
                                                   const int* __restrict__ qt,
                                                   float* __restrict__ out) {
    const long LOFF[4] = {0L, 131072L, 163840L, 172032L};
    const float INV_SQRT_C = 0.08838834764831845f;   // 1/sqrt(128)

    int plane = blockIdx.y;
    int sn = blockIdx.x;                  // s*N + n
    int n = sn & (N - 1);
    int sfr = sn >> 9;
    int tid = threadIdx.x;
    int warp = tid >> 5, lane = tid & 31;
    int sub = lane >> 4;                  // which of 2 positions this half-warp reads
    int lh  = lane & 15;                  // lane within half-warp: channels lh*8..+7

    __shared__ float t_sh[C];
    __shared__ float patch[4][64];

    const __half* __restrict__ pbase = g_pyr[plane];

    float cx, cy;
    {
        const float* __restrict__ cp = coords + (long)sn * 3;
        float x = cp[0], y = cp[1], z = cp[2];
        if (plane == 0)      { cx = x; cy = y; }
        else if (plane == 1) { cx = y; cy = z; }
        else                 { cx = x; cy = z; }
    }

    // --- inline tfeat: bilinear at frame qt[n] with frame-0 coords ---
    {
        const float* __restrict__ cp0 = coords + (long)n * 3;   // s = 0
        float x = cp0[0], y = cp0[1], z = cp0[2];
        float fx, fy;
        if (plane == 0)      { fx = x; fy = y; }
        else if (plane == 1) { fx = y; fy = z; }
        else                 { fx = x; fy = z; }
        fx = fminf(fmaxf(fx, 0.f), (float)(W - 1));
        fy = fminf(fmaxf(fy, 0.f), (float)(H - 1));
        int qx0 = min((int)floorf(fx), W - 2);
        int qy0 = min((int)floorf(fy), H - 2);
        float wx = fx - (float)qx0, wy = fy - (float)qy0;
        int t = qt[n];
        const __half* __restrict__ b = pbase + (((long)t * H + qy0) * W + qx0) * C + tid;
        float v00 = __half2float(b[0]), v01 = __half2float(b[C]);
        float v10 = __half2float(b[(long)W * C]), v11 = __half2float(b[(long)W * C + C]);
        t_sh[tid] = v00 * (1.f - wx) * (1.f - wy) + v01 * wx * (1.f - wy)
                  + v10 * (1.f - wx) * wy + v11 * wx * wy;
    }
    __syncthreads();
    // 8 target channels for this lane's slice
    float4 tA = *(const float4*)&t_sh[lh * 8];
    float4 tB = *(const float4*)&t_sh[lh * 8 + 4];

    float* __restrict__ outcorr = out + (long)sn * OUT_F + plane * (LEVELS * KK);

    // --- warp 'warp' handles level l = warp ---
    {
        int l = warp;
        int Wl = W >> l;
        float inv = 1.0f / (float)(1 << l);
        float cxl = cx * inv, cyl = cy * inv;

        // patch base corner (tap j=0)
        float xs0 = fminf(fmaxf(cxl - 3.f, 0.f), (float)(Wl - 1));
        int xb = min((int)floorf(xs0), Wl - 2);
        float ys0 = fminf(fmaxf(cyl - 3.f, 0.f), (float)(Wl - 1));
        int yb = min((int)floorf(ys0), Wl - 2);

        long fr = LOFF[l] + (long)sfr * Wl * Wl;

        // 64 patch dots; 2 positions per iter (one per half-warp)
#pragma unroll 8
        for (int i = 0; i < 32; ++i) {
            int p = i * 2 + sub;
            int iy = p >> 3, ix = p & 7;
            int xx = min(xb + ix, Wl - 1);
            int yy = min(yb + iy, Wl - 1);
            const uint4 u = *(const uint4*)(pbase + (fr + (long)yy * Wl + xx) * C + lh * 8);
            float2 f0 = __half22float2(*(const __half2*)&u.x);
            float2 f1 = __half22float2(*(const __half2*)&u.y);
            float2 f2 = __half22float2(*(const __half2*)&u.z);
            float2 f3 = __half22float2(*(const __half2*)&u.w);
            float d = f0.x * tA.x + f0.y * tA.y + f1.x * tA.z + f1.y * tA.w
                    + f2.x * tB.x + f2.y * tB.y + f3.x * tB.z + f3.y * tB.w;
            d += __shfl_xor_sync(0xffffffffu, d, 8);
            d += __shfl_xor_sync(0xffffffffu, d, 4);
            d += __shfl_xor_sync(0xffffffffu, d, 2);
            d += __shfl_xor_sync(0xffffffffu, d, 1);
            if (lh == 0) patch[l][p] = d * INV_SQRT_C;
        }
        __syncwarp();

        // 49 bilinear taps; weights recomputed scalar per tap
        const float* __restrict__ pl = patch[l];
#pragma unroll
        for (int k0 = 0; k0 < 64; k0 += 32) {
            int k = k0 + lane;
            if (k < KK) {
                int ky = k / 7, kx = k - ky * 7;
                float xsk = fminf(fmaxf(cxl + (float)(kx - 3), 0.f), (float)(Wl - 1));
                int xk0 = min((int)floorf(xsk), Wl - 2);
                float wx = xsk - (float)xk0;
                float ysk = fminf(fmaxf(cyl + (float)(ky - 3), 0.f), (float)(Wl - 1));
                int yk0 = min((int)floorf(ysk), Wl - 2);
                float wy = ysk - (float)yk0;
                int ix = xk0 - xb, iy = yk0 - yb;
                float v = pl[iy * 8 + ix]           * (1.f - wx) * (1.f - wy)
                        + pl[iy * 8 + ix + 1]       * wx         * (1.f - wy)
                        + pl[(iy + 1) * 8 + ix]     * (1.f - wx) * wy
                        + pl[(iy + 1) * 8 + ix + 1] * wx         * wy;
                outcorr[l * KK + k] = v;
            }
        }
    }

    // current triplane feature: bilinear at level 0, frame s (independent of patch)
    {
        float xs = fminf(fmaxf(cx, 0.f), (float)(W - 1));
        float ys = fminf(fmaxf(cy, 0.f), (float)(H - 1));
        int x0 = min((int)floorf(xs), W - 2);
        int y0 = min((int)floorf(ys), H - 2);
        float wx = xs - (float)x0, wy = ys - (float)y0;
        const __half* __restrict__ b = pbase + (((long)sfr * H + y0) * W + x0) * C + tid;
        float v00 = __half2float(b[0]), v01 = __half2float(b[C]);
        float v10 = __half2float(b[(long)W * C]), v11 = __half2float(b[(long)W * C + C]);
        float v = v00 * (1.f - wx) * (1.f - wy) + v01 * wx * (1.f - wy)
                + v10 * (1.f - wx) * wy + v11 * wx * wy;
        out[(long)sn * OUT_F + 3 * LEVELS * KK + plane * C + tid] = v;
    }
}

// ---------------------------------------------------------------------------
extern "C" void kernel_launch(void* const* d_in, const int* in_sizes, int n_in,
                              void* d_out, int out_size) {
    const float* fxy    = (const float*)d_in[0];
    const float* fyz    = (const float*)d_in[1];
    const float* fxz    = (const float*)d_in[2];
    const float* coords = (const float*)d_in[3];
    const int*   qt     = (const int*)d_in[4];
    float* out = (float*)d_out;
    (void)in_sizes; (void)n_in; (void)out_size;

    // 1) fused transpose + L1 pool (fp32 -> fp16)
    {
        dim3 grid(S * 64, 16, 3), block(32, 8);
        transpose_pool_kernel<<<grid, block>>>(fxy, fyz, fxz);
    }
    // 2) fused L2+L3 pools
    {
        dim3 grid(S * 16, 1, 3);
        pool23_kernel<<<grid, 256>>>();
    }
    // 3) main lookup (tfeat inlined, warp-per-level)
    {
        dim3 grid(S * N, 3);
        main_kernel<<<grid, 128>>>(coords, qt, out);
    }
}